// round 10
// baseline (speedup 1.0000x reference)
#include <cuda_runtime.h>
#include <math.h>

// ---------------------------------------------------------------------------
// B=8, CIN=64, COUT=64, H=W=128, R=2, HID=8, K=3, GK=15
// ---------------------------------------------------------------------------
#define BB   8
#define CIN  64
#define COUT 64
#define HH   128
#define WW   128
#define RR   2
#define HID  8
#define HW   (HH*WW)          // 16384

// ---------------------------------------------------------------------------
// Device scratch (no allocation allowed)
// ---------------------------------------------------------------------------
__device__ float g_pooled[BB*CIN*9];                 // [b][ci][yx]
// conv weights, layout [b][r][ci][kyx(9)][co]  (co fastest -> packed pairs)
__device__ float g_kern[(size_t)BB*RR*CIN*9*COUT];   // 589824 floats
__device__ float g_sa[BB*HW];
__device__ float g_pmin[BB*16];                      // per-tile sa min partials
__device__ float g_pmax[BB*16];

// ---------------------------------------------------------------------------
// 1) Merged pool + sa kernel (independent work, one launch).
// ---------------------------------------------------------------------------
__global__ __launch_bounds__(256) void poolsa_kernel(const float* __restrict__ feat,
                                                     const float* __restrict__ pred,
                                                     const float* __restrict__ gk) {
    const int bid = blockIdx.x;
    const int tid = threadIdx.x;

    if (bid < 512) {
        // ---------------- pool part (float4 vectorized) ----------------
        __shared__ float red[9][256];
        const float4* src4 = (const float4*)(feat + (size_t)bid * HW);
        float a[9];
        #pragma unroll
        for (int i = 0; i < 9; ++i) a[i] = 0.f;

        for (int idx = tid; idx < HW/4; idx += 256) {
            float4 v4 = src4[idx];
            int y = idx >> 5;                 // 32 float4 per row
            int x0q = (idx & 31) * 4;
            bool rm0 = (y < 43), rm1 = (y >= 42) & (y < 86), rm2 = (y >= 85);
            float vv[4] = {v4.x, v4.y, v4.z, v4.w};
            #pragma unroll
            for (int e = 0; e < 4; ++e) {
                int x = x0q + e;
                float v = vv[e];
                bool cm0 = (x < 43), cm1 = (x >= 42) & (x < 86), cm2 = (x >= 85);
                if (rm0) { if (cm0) a[0]+=v; if (cm1) a[1]+=v; if (cm2) a[2]+=v; }
                if (rm1) { if (cm0) a[3]+=v; if (cm1) a[4]+=v; if (cm2) a[5]+=v; }
                if (rm2) { if (cm0) a[6]+=v; if (cm1) a[7]+=v; if (cm2) a[8]+=v; }
            }
        }
        #pragma unroll
        for (int k = 0; k < 9; ++k) red[k][tid] = a[k];
        __syncthreads();
        for (int s = 128; s > 0; s >>= 1) {
            if (tid < s) {
                #pragma unroll
                for (int k = 0; k < 9; ++k)
                    red[k][tid] += red[k][tid + s];
            }
            __syncthreads();
        }
        if (tid < 9) {
            const float cnt[3] = {43.f, 44.f, 43.f};
            int i = tid / 3, j = tid % 3;
            g_pooled[bid*9 + tid] = red[tid][0] / (cnt[i] * cnt[j]);
        }
    } else {
        // ---------------- sa part ----------------
        __shared__ float sp[46][46];
        __shared__ float sg[225];
        __shared__ float rmn[8], rmx[8];
        const int t  = bid - 512;            // 0..127
        const int b  = t >> 4;
        const int rem = t & 15;
        const int y0 = (rem >> 2) * 32, x0 = (rem & 3) * 32;

        for (int i = tid; i < 225; i += 256) sg[i] = gk[i];
        for (int i = tid; i < 46*46; i += 256) {
            int ly = i / 46, lx = i % 46;
            int gy = y0 - 7 + ly, gx = x0 - 7 + lx;
            float v = 0.f;
            if ((unsigned)gy < 128u && (unsigned)gx < 128u) {
                float pv = pred[b*HW + gy*128 + gx];
                v = 1.f / (1.f + expf(-pv));
            }
            sp[ly][lx] = v;
        }
        __syncthreads();

        float tmn = 3.4e38f, tmx = 0.f;   // sa >= 0
        #pragma unroll
        for (int p = 0; p < 4; ++p) {
            int id = tid + p*256;
            int py = id >> 5, px = id & 31;
            float s = 0.f;
            for (int u = 0; u < 15; ++u) {
                #pragma unroll
                for (int v = 0; v < 15; ++v)
                    s += sp[py + u][px + v] * sg[u*15 + v];
            }
            g_sa[b*HW + (y0 + py)*128 + (x0 + px)] = s;
            tmn = fminf(tmn, s); tmx = fmaxf(tmx, s);
        }
        #pragma unroll
        for (int o = 16; o; o >>= 1) {
            tmn = fminf(tmn, __shfl_xor_sync(0xffffffffu, tmn, o));
            tmx = fmaxf(tmx, __shfl_xor_sync(0xffffffffu, tmx, o));
        }
        if ((tid & 31) == 0) { rmn[tid >> 5] = tmn; rmx[tid >> 5] = tmx; }
        __syncthreads();
        if (tid == 0) {
            #pragma unroll
            for (int w = 0; w < 8; ++w) { tmn = fminf(tmn, rmn[w]); tmx = fmaxf(tmx, rmx[w]); }
            g_pmin[b*16 + (y0 >> 5)*4 + (x0 >> 5)] = tmn;
            g_pmax[b*16 + (y0 >> 5)*4 + (x0 >> 5)] = tmx;
        }
    }
}

// ---------------------------------------------------------------------------
// 2) Fused MLP1 + kernel generation.  Block = (b, r, yx), 144 blocks.
// ---------------------------------------------------------------------------
__global__ void kerngen_kernel(const float* __restrict__ w1,
                               const float* __restrict__ b1,
                               const float* __restrict__ w2,
                               const float* __restrict__ b2) {
    const int blk = blockIdx.x;               // 0..143
    const int b = blk / 18, rem = blk % 18;
    const int r = rem / 9, yx = rem % 9;

    __shared__ float hs[8];
    if (threadIdx.x < 8) {
        const int c = r*8 + threadIdx.x;
        float v = b1[c];
        #pragma unroll 8
        for (int ci = 0; ci < CIN; ++ci)
            v += w1[c*CIN + ci] * g_pooled[(b*CIN + ci)*9 + yx];
        hs[threadIdx.x] = 1.f / (1.f + expf(-v));
    }
    __syncthreads();

    for (int idx = threadIdx.x; idx < CIN*COUT; idx += 256) {
        const int co = idx & 63, ci = idx >> 6;
        const int q = r*(CIN*COUT) + co*CIN + ci;
        const float* wp = w2 + (size_t)q * HID;
        float v = b2[q];
        #pragma unroll
        for (int h = 0; h < HID; ++h) v += wp[h] * hs[h];
        g_kern[((size_t)(b*2 + r)*CIN + ci)*576 + yx*64 + co] = v;
    }
}

// ---------------------------------------------------------------------------
// 3) Main dynamic conv (256 threads, 4px x 16co): weight-only register
//    double buffer (fits 128-reg cap -> no spills), feat loaded per
//    iteration (stall covered by 4 warps/SMSP oversubscribing the fma pipe).
//
//    Dynamic smem layout:
//      [0      , 20736)  s_feat[2][8][18][18]
//      [20736  , 94464)  s_w  [2][2][8][9][64]   (buf, r, ci, k, co)
// ---------------------------------------------------------------------------
#define FEAT_BUF_B 10368u
#define W_BUF_B    36864u
#define W_R_B      18432u

extern __shared__ __align__(16) char dsm[];

#define LOADW(i, a)                                                               \
  asm volatile("ld.shared.v2.b64 {%0,%1},[%2];"    : "=l"(w[i][0]), "=l"(w[i][1]) : "r"(a)); \
  asm volatile("ld.shared.v2.b64 {%0,%1},[%2+16];" : "=l"(w[i][2]), "=l"(w[i][3]) : "r"(a)); \
  asm volatile("ld.shared.v2.b64 {%0,%1},[%2+32];" : "=l"(w[i][4]), "=l"(w[i][5]) : "r"(a)); \
  asm volatile("ld.shared.v2.b64 {%0,%1},[%2+48];" : "=l"(w[i][6]), "=l"(w[i][7]) : "r"(a));

#define LOADF(off)                                                                \
  { float _a, _b, _c, _d;                                                         \
    asm volatile("ld.shared.f32 %0,[%1];" : "=f"(_a) : "r"(fa0 + (off)));         \
    asm volatile("ld.shared.f32 %0,[%1];" : "=f"(_b) : "r"(fa1 + (off)));         \
    asm volatile("ld.shared.f32 %0,[%1];" : "=f"(_c) : "r"(fa2 + (off)));         \
    asm volatile("ld.shared.f32 %0,[%1];" : "=f"(_d) : "r"(fa3 + (off)));         \
    asm("mov.b64 %0,{%1,%1};" : "=l"(fp[0]) : "f"(_a));                           \
    asm("mov.b64 %0,{%1,%1};" : "=l"(fp[1]) : "f"(_b));                           \
    asm("mov.b64 %0,{%1,%1};" : "=l"(fp[2]) : "f"(_c));                           \
    asm("mov.b64 %0,{%1,%1};" : "=l"(fp[3]) : "f"(_d)); }

// One ci iteration (9 taps). PAR = parity of this ci within the chunk;
// LASTC clamps the final weight prefetch to an in-bounds address.
#define CI_STEP(PAR, LASTC)                                                       \
  { _Pragma("unroll")                                                             \
    for (int k = 0; k < 9; ++k) {                                                 \
      const int cur = (k + (PAR)) & 1, nxt = cur ^ 1;                             \
      LOADF(TAPOFF[k]);                                                           \
      unsigned wn = (k < 8) ? (wa + (unsigned)(k + 1) * 256u)                     \
                            : ((LASTC) ? wa : wa + 2304u);                        \
      LOADW(nxt, wn);                                                             \
      _Pragma("unroll")                                                           \
      for (int q = 0; q < 8; ++q) {                                               \
        asm("fma.rn.f32x2 %0,%1,%2,%0;" : "+l"(acc[0][q]) : "l"(fp[0]), "l"(w[cur][q])); \
        asm("fma.rn.f32x2 %0,%1,%2,%0;" : "+l"(acc[1][q]) : "l"(fp[1]), "l"(w[cur][q])); \
        asm("fma.rn.f32x2 %0,%1,%2,%0;" : "+l"(acc[2][q]) : "l"(fp[2]), "l"(w[cur][q])); \
        asm("fma.rn.f32x2 %0,%1,%2,%0;" : "+l"(acc[3][q]) : "l"(fp[3]), "l"(w[cur][q])); \
      }                                                                           \
    } }

__global__ __launch_bounds__(256, 2)
void conv_main_kernel(const float* __restrict__ feat,
                      const float* __restrict__ pred,
                      float* __restrict__ out) {
    __shared__ int s_bucket[64];
    __shared__ int s_prefix[65];
    __shared__ __align__(4) unsigned char s_perm[256];

    const unsigned featsm = (unsigned)__cvta_generic_to_shared(dsm);
    const unsigned wsm    = featsm + 2u*FEAT_BUF_B;

    const int tid = threadIdx.x;
    const int b  = blockIdx.z;
    const int x0 = blockIdx.x * 16;
    const int y0 = blockIdx.y * 16;

    // ---- per-image sa min/max (16 partials, L2-broadcast) ----
    float mn = 3.4e38f, mx = 0.f;
    #pragma unroll
    for (int i = 0; i < 16; ++i) {
        mn = fminf(mn, g_pmin[b*16 + i]);
        mx = fmaxf(mx, g_pmax[b*16 + i]);
    }

    // ---- r per pixel + bank-aware counting sort ----
    if (tid < 64) s_bucket[tid] = 0;
    __syncthreads();
    int key, rank;
    {
        int py = tid >> 4, px = tid & 15;
        int pix = b*HW + (y0 + py)*128 + (x0 + px);
        float sa = (g_sa[pix] - mn) / (mx - mn + 1e-8f);
        float pv = 1.f / (1.f + expf(-pred[pix]));
        int r = (fmaxf(sa, pv) < 0.5f) ? 1 : 0;   // argmax([h,1-h])
        int bank = (py*18 + px) & 31;             // smem bank of this pixel
        key = r*32 + bank;
        rank = atomicAdd(&s_bucket[key], 1);
    }
    __syncthreads();
    if (tid == 0) {
        int a = 0;
        #pragma unroll 8
        for (int i = 0; i < 64; ++i) { s_prefix[i] = a; a += s_bucket[i]; }
        s_prefix[64] = a;
    }
    __syncthreads();
    s_perm[s_prefix[key] + rank] = (unsigned char)tid;
    const int n0 = s_prefix[32];
    __syncthreads();

    // ---- my 4 compacted pixels, 16 couts ----
    const int p   = tid & 63;
    const int cog = tid >> 6;
    uchar4 ids = *(const uchar4*)&s_perm[p*4];
    const int yA = ids.x >> 4, xA = ids.x & 15;
    const int yB = ids.y >> 4, xB = ids.y & 15;
    const int yC = ids.z >> 4, xC = ids.z & 15;
    const int yD = ids.w >> 4, xD = ids.w & 15;
    const unsigned pb0 = featsm + (unsigned)(yA*18 + xA)*4u;
    const unsigned pb1 = featsm + (unsigned)(yB*18 + xB)*4u;
    const unsigned pb2 = featsm + (unsigned)(yC*18 + xC)*4u;
    const unsigned pb3 = featsm + (unsigned)(yD*18 + xD)*4u;
    // straddler thread (4p < n0 < 4p+4) uses r=0; its r=1 slots fixed later
    const int rt = (4*p >= n0) ? 1 : 0;

    const unsigned wbU = wsm + (unsigned)cog * 64u + (unsigned)rt * W_R_B;
    const unsigned TAPOFF[9] = {0u,4u,8u,72u,76u,80u,144u,148u,152u};

    unsigned long long acc[4][8];
    #pragma unroll
    for (int i = 0; i < 4; ++i)
        #pragma unroll
        for (int j = 0; j < 8; ++j) acc[i][j] = 0ull;

    // ------------- staging helper (cp.async, zero-fill OOB) -------------
    auto stage_chunk = [&](int cc, int buf) {
        const float* fsrc = feat + ((size_t)(b*CIN + cc*8)) * HW;
        #pragma unroll 1
        for (int i = tid; i < 2592; i += 256) {
            int ci = i / 324, rem = i - ci*324;
            int ly = rem / 18, lx = rem - ly*18;
            int gy = y0 - 1 + ly, gx = x0 - 1 + lx;
            bool v = ((unsigned)gy < 128u) & ((unsigned)gx < 128u);
            const float* src = v ? (fsrc + ci*HW + gy*128 + gx) : fsrc;
            unsigned dst = featsm + (unsigned)buf*FEAT_BUF_B + (unsigned)i*4u;
            asm volatile("cp.async.ca.shared.global [%0], [%1], 4, %2;"
                         :: "r"(dst), "l"(src), "r"(v ? 4 : 0));
        }
        const float4* w0p = (const float4*)(g_kern + ((size_t)(b*2 + 0)*CIN + cc*8)*576);
        const float4* w1p = (const float4*)(g_kern + ((size_t)(b*2 + 1)*CIN + cc*8)*576);
        const unsigned wb = wsm + (unsigned)buf*W_BUF_B;
        #pragma unroll 1
        for (int i = tid; i < 1152; i += 256) {
            asm volatile("cp.async.cg.shared.global [%0], [%1], 16;"
                         :: "r"(wb + (unsigned)i*16u), "l"(w0p + i));
            asm volatile("cp.async.cg.shared.global [%0], [%1], 16;"
                         :: "r"(wb + W_R_B + (unsigned)i*16u), "l"(w1p + i));
        }
        asm volatile("cp.async.commit_group;");
    };

    stage_chunk(0, 0);

    for (int cc = 0; cc < 8; ++cc) {
        const int buf = cc & 1;
        if (cc < 7) {
            stage_chunk(cc + 1, buf ^ 1);
            asm volatile("cp.async.wait_group 1;");
        } else {
            asm volatile("cp.async.wait_group 0;");
        }
        __syncthreads();

        unsigned wa  = wbU + (unsigned)buf*W_BUF_B;
        unsigned fa0 = pb0 + (unsigned)buf*FEAT_BUF_B;
        unsigned fa1 = pb1 + (unsigned)buf*FEAT_BUF_B;
        unsigned fa2 = pb2 + (unsigned)buf*FEAT_BUF_B;
        unsigned fa3 = pb3 + (unsigned)buf*FEAT_BUF_B;

        unsigned long long w[2][8];
        unsigned long long fp[4];
        LOADW(0, wa);

        #pragma unroll 1
        for (int ci2 = 0; ci2 < 4; ++ci2) {
            CI_STEP(0, false)
            wa += 2304u; fa0 += 1296u; fa1 += 1296u; fa2 += 1296u; fa3 += 1296u;
            CI_STEP(1, (ci2 == 3))
            wa += 2304u; fa0 += 1296u; fa1 += 1296u; fa2 += 1296u; fa3 += 1296u;
        }
        __syncthreads();   // protect buf from next stage overwrite
    }

    // ---- epilogue: write only slots whose r matches rt ----
    const int poff[4] = {(y0+yA)*128 + x0+xA, (y0+yB)*128 + x0+xB,
                         (y0+yC)*128 + x0+xC, (y0+yD)*128 + x0+xD};
    bool wr[4];
    #pragma unroll
    for (int i2 = 0; i2 < 4; ++i2)
        wr[i2] = (((4*p + i2 >= n0) ? 1 : 0) == rt);
    #pragma unroll
    for (int j = 0; j < 8; ++j) {
        const int co = cog*16 + 2*j;
        float* o0 = out + ((size_t)(b*COUT + co)) * HW;
        #pragma unroll
        for (int i2 = 0; i2 < 4; ++i2) {
            if (wr[i2]) {
                float lo, hi;
                asm("mov.b64 {%0,%1},%2;" : "=f"(lo), "=f"(hi) : "l"(acc[i2][j]));
                o0[poff[i2]]      = lo;
                o0[poff[i2] + HW] = hi;
            }
        }
    }

    // ---- fix-up: recompute the <=3 straddler r=1 pixels directly ----
    const int h = n0 & 3;                 // 0 -> no straddler
    if (h && tid < 64*(4 - h)) {
        const int j  = tid >> 6;          // 0..(4-h-1)
        const int co = tid & 63;
        const int id = s_perm[n0 + j];
        const int gy = y0 + (id >> 4), gx = x0 + (id & 15);
        const float* fb = feat + (size_t)b*CIN*HW;
        const float* wb = g_kern + ((size_t)(b*2 + 1))*CIN*576;
        float sum = 0.f;
        #pragma unroll 1
        for (int ci = 0; ci < CIN; ++ci) {
            const float* fpp = fb + ci*HW;
            const float* wp = wb + ci*576 + co;
            #pragma unroll
            for (int k = 0; k < 9; ++k) {
                const int ky = k / 3, kx = k - ky*3;
                const int yy = gy + ky - 1, xx = gx + kx - 1;
                float fv = 0.f;
                if ((unsigned)yy < 128u && (unsigned)xx < 128u)
                    fv = fpp[yy*128 + xx];
                sum += fv * wp[k*64];
            }
        }
        out[((size_t)(b*COUT + co))*HW + gy*128 + gx] = sum;
    }
}

// ---------------------------------------------------------------------------
// Launch: inputs in metadata order: feat, pred, w1, b1, w2, b2, gk
// ---------------------------------------------------------------------------
#define CONV_DSMEM (2*10368 + 2*36864)   /* 94464 B */

extern "C" void kernel_launch(void* const* d_in, const int* in_sizes, int n_in,
                              void* d_out, int out_size) {
    const float* feat = (const float*)d_in[0];
    const float* pred = (const float*)d_in[1];
    const float* w1   = (const float*)d_in[2];
    const float* b1   = (const float*)d_in[3];
    const float* w2   = (const float*)d_in[4];
    const float* b2   = (const float*)d_in[5];
    const float* gk   = (const float*)d_in[6];
    float* out = (float*)d_out;

    cudaFuncSetAttribute(conv_main_kernel,
                         cudaFuncAttributeMaxDynamicSharedMemorySize, CONV_DSMEM);

    poolsa_kernel<<<640, 256>>>(feat, pred, gk);
    kerngen_kernel<<<BB*RR*9, 256>>>(w1, b1, w2, b2);

    dim3 gc(8, 8, BB);
    conv_main_kernel<<<gc, 256, CONV_DSMEM>>>(feat, pred, out);
}

// round 13
// speedup vs baseline: 1.2900x; 1.2900x over previous
#include <cuda_runtime.h>
#include <cuda_bf16.h>
#include <math.h>
#include <stdint.h>

#define BB   8
#define CIN  64
#define COUT 64
#define HH   128
#define WW   128
#define HID  8
#define HW   (HH*WW)

// ---------------------------------------------------------------------------
// Device scratch
// ---------------------------------------------------------------------------
__device__ float g_pooled[BB*CIN*9];
// bf16 B tiles for mma: slab = (b*9+j)*2+split, layout [n=128][kk=64] bf16
__device__ __align__(16) unsigned char g_kbf[(size_t)BB*9*2*16384];
__device__ float g_sa[BB*HW];
__device__ float g_pmin[BB*16];
__device__ float g_pmax[BB*16];

// ---------------------------------------------------------------------------
// 1) pool + sa (proven kernel, unchanged)
// ---------------------------------------------------------------------------
__global__ __launch_bounds__(256) void poolsa_kernel(const float* __restrict__ feat,
                                                     const float* __restrict__ pred,
                                                     const float* __restrict__ gk) {
    const int bid = blockIdx.x, tid = threadIdx.x;
    if (bid < 512) {
        __shared__ float red[9][256];
        const float* src = feat + (size_t)bid * HW;
        float a[9];
        #pragma unroll
        for (int i = 0; i < 9; ++i) a[i] = 0.f;
        for (int idx = tid; idx < HW; idx += 256) {
            float v = src[idx];
            int y = idx >> 7, x = idx & 127;
            bool rm0 = (y < 43), rm1 = (y >= 42) & (y < 86), rm2 = (y >= 85);
            bool cm0 = (x < 43), cm1 = (x >= 42) & (x < 86), cm2 = (x >= 85);
            if (rm0) { if (cm0) a[0]+=v; if (cm1) a[1]+=v; if (cm2) a[2]+=v; }
            if (rm1) { if (cm0) a[3]+=v; if (cm1) a[4]+=v; if (cm2) a[5]+=v; }
            if (rm2) { if (cm0) a[6]+=v; if (cm1) a[7]+=v; if (cm2) a[8]+=v; }
        }
        #pragma unroll
        for (int k = 0; k < 9; ++k) red[k][tid] = a[k];
        __syncthreads();
        for (int s = 128; s > 0; s >>= 1) {
            if (tid < s) {
                #pragma unroll
                for (int k = 0; k < 9; ++k) red[k][tid] += red[k][tid + s];
            }
            __syncthreads();
        }
        if (tid < 9) {
            const float cnt[3] = {43.f, 44.f, 43.f};
            g_pooled[bid*9 + tid] = red[tid][0] / (cnt[tid/3] * cnt[tid%3]);
        }
    } else {
        __shared__ float sp[46][46];
        __shared__ float sg[225];
        __shared__ float rmn[8], rmx[8];
        const int t = bid - 512, b = t >> 4, rem = t & 15;
        const int y0 = (rem >> 2) * 32, x0 = (rem & 3) * 32;
        for (int i = tid; i < 225; i += 256) sg[i] = gk[i];
        for (int i = tid; i < 46*46; i += 256) {
            int ly = i / 46, lx = i % 46;
            int gy = y0 - 7 + ly, gx = x0 - 7 + lx;
            float v = 0.f;
            if ((unsigned)gy < 128u && (unsigned)gx < 128u)
                v = 1.f / (1.f + expf(-pred[b*HW + gy*128 + gx]));
            sp[ly][lx] = v;
        }
        __syncthreads();
        float tmn = 3.4e38f, tmx = 0.f;
        #pragma unroll
        for (int p = 0; p < 4; ++p) {
            int id = tid + p*256, py = id >> 5, px = id & 31;
            float s = 0.f;
            for (int u = 0; u < 15; ++u)
                #pragma unroll
                for (int v = 0; v < 15; ++v)
                    s += sp[py + u][px + v] * sg[u*15 + v];
            g_sa[b*HW + (y0 + py)*128 + (x0 + px)] = s;
            tmn = fminf(tmn, s); tmx = fmaxf(tmx, s);
        }
        #pragma unroll
        for (int o = 16; o; o >>= 1) {
            tmn = fminf(tmn, __shfl_xor_sync(0xffffffffu, tmn, o));
            tmx = fmaxf(tmx, __shfl_xor_sync(0xffffffffu, tmx, o));
        }
        if ((tid & 31) == 0) { rmn[tid >> 5] = tmn; rmx[tid >> 5] = tmx; }
        __syncthreads();
        if (tid == 0) {
            #pragma unroll
            for (int w = 0; w < 8; ++w) { tmn = fminf(tmn, rmn[w]); tmx = fmaxf(tmx, rmx[w]); }
            g_pmin[b*16 + (y0 >> 5)*4 + (x0 >> 5)] = tmn;
            g_pmax[b*16 + (y0 >> 5)*4 + (x0 >> 5)] = tmx;
        }
    }
}

// ---------------------------------------------------------------------------
// 2) kerngen: MLP + emit bf16 hi/lo B tiles [n=r*64+co][kk] per K-chunk slab
// ---------------------------------------------------------------------------
__global__ void kerngen_kernel(const float* __restrict__ w1,
                               const float* __restrict__ b1,
                               const float* __restrict__ w2,
                               const float* __restrict__ b2) {
    const int blk = blockIdx.x;               // 0..143 = (b, r, yx)
    const int b = blk / 18, rem = blk % 18;
    const int r = rem / 9, yx = rem % 9;
    __shared__ float hs[8];
    if (threadIdx.x < 8) {
        const int c = r*8 + threadIdx.x;
        float v = b1[c];
        #pragma unroll 8
        for (int ci = 0; ci < CIN; ++ci)
            v += w1[c*CIN + ci] * g_pooled[(b*CIN + ci)*9 + yx];
        hs[threadIdx.x] = 1.f / (1.f + expf(-v));
    }
    __syncthreads();
    for (int idx = threadIdx.x; idx < CIN*COUT; idx += 256) {
        const int co = idx & 63, ci = idx >> 6;
        const int q = r*(CIN*COUT) + co*CIN + ci;
        const float* wp = w2 + (size_t)q * HID;
        float v = b2[q];
        #pragma unroll
        for (int h = 0; h < HID; ++h) v += wp[h] * hs[h];
        __nv_bfloat16 hi = __float2bfloat16(v);
        __nv_bfloat16 lo = __float2bfloat16(v - __bfloat162float(hi));
        int K = ci*9 + yx, j = K >> 6, kk = K & 63;
        int n = r*64 + co;
        size_t base = ((size_t)((b*9 + j)*2))*16384 + (size_t)n*128 + kk*2;
        *(unsigned short*)(g_kbf + base)         = __bfloat16_as_ushort(hi);
        *(unsigned short*)(g_kbf + base + 16384) = __bfloat16_as_ushort(lo);
    }
}

// ---------------------------------------------------------------------------
// 3) conv: mma.sync bf16 3-term implicit GEMM. Block=(y,b), 256 thr, 8 warps.
//    D[128px,128n] (n = r*64+co, both r), K=576 in 9 chunks of 64.
//    smem rows padded to 144B -> conflict-free ldmatrix, no swizzle.
//    B ldmatrix tiles cover 16 n-rows each -> stride 2304 B (FIXED from R12).
// ---------------------------------------------------------------------------
#define A_HI 0u
#define A_LO 18432u
#define B_HI 36864u
#define B_LO 55296u
#define FC_OFF 73728u
#define CONV_DSMEM 86400

extern __shared__ __align__(16) unsigned char dsm[];

#define LDSM4(r0,r1,r2,r3,a) \
    asm volatile("ldmatrix.sync.aligned.m8n8.x4.shared.b16 {%0,%1,%2,%3},[%4];" \
        : "=r"(r0),"=r"(r1),"=r"(r2),"=r"(r3) : "r"(a))

#define MMA(d, a, b0, b1)                                                       \
    asm volatile("mma.sync.aligned.m16n8k16.row.col.f32.bf16.bf16.f32 "         \
        "{%0,%1,%2,%3},{%4,%5,%6,%7},{%8,%9},{%0,%1,%2,%3};"                    \
        : "+f"((d)[0]),"+f"((d)[1]),"+f"((d)[2]),"+f"((d)[3])                   \
        : "r"((a)[0]),"r"((a)[1]),"r"((a)[2]),"r"((a)[3]),"r"(b0),"r"(b1))

__global__ __launch_bounds__(256, 2)
void conv_main_kernel(const float* __restrict__ feat,
                      const float* __restrict__ pred,
                      float* __restrict__ out) {
    __shared__ unsigned char s_rsel[128];

    const int tid = threadIdx.x;
    const int wid = tid >> 5, l = tid & 31;
    const int y = blockIdx.x, b = blockIdx.y;
    const unsigned smb = (unsigned)__cvta_generic_to_shared(dsm);
    float* fc = (float*)(dsm + FC_OFF);

    // per-pixel r for this image row
    if (tid < 128) {
        float mn = 3.4e38f, mx = 0.f;
        #pragma unroll
        for (int i = 0; i < 16; ++i) {
            mn = fminf(mn, g_pmin[b*16 + i]);
            mx = fmaxf(mx, g_pmax[b*16 + i]);
        }
        int pix = b*HW + y*128 + tid;
        float sa = (g_sa[pix] - mn) / (mx - mn + 1e-8f);
        float pv = 1.f / (1.f + expf(-pred[pix]));
        s_rsel[tid] = (fmaxf(sa, pv) < 0.5f) ? 1 : 0;   // argmax([h,1-h])
    }

    const int warpM = wid >> 1, warpN = wid & 1;       // 4x2 warp grid
    // ldmatrix per-lane row offsets (144B rows)
    const unsigned arow = (unsigned)((warpM*32 + (l & 15))*144 + ((l >> 4)*16));
    const unsigned brow = (unsigned)((warpN*64 + (l & 7) + ((l >> 4) << 3))*144
                                     + (((l >> 3) & 1)*16));
    const int kk2 = tid & 31, qq = tid >> 5;           // A-build mapping

    float acc[2][8][4];
    #pragma unroll
    for (int mt = 0; mt < 2; ++mt)
        #pragma unroll
        for (int nt = 0; nt < 8; ++nt)
            #pragma unroll
            for (int e = 0; e < 4; ++e) acc[mt][nt][e] = 0.f;

    for (int j = 0; j < 9; ++j) {
        const int ci0 = (64*j) / 9;
        __syncthreads();   // protect smem from previous chunk's readers
        // ---- stage fp32 halo cache (zero-filled OOB) ----
        for (int i = tid; i < 3168; i += 256) {
            int ci = i / 396, rem = i - ci*396;
            int row = rem / 132, xi = rem - row*132;
            int x = xi - 1, ry = y + row - 1;
            bool v = ((unsigned)x < 128u) & ((unsigned)ry < 128u);
            const float* src = feat + ((size_t)(b*CIN + ci0 + ci))*HW
                             + (v ? (ry*128 + x) : 0);
            asm volatile("cp.async.ca.shared.global [%0],[%1],4,%2;"
                         :: "r"(smb + FC_OFF + (unsigned)i*4u), "l"(src), "r"(v ? 4 : 0));
        }
        // ---- stage B hi/lo into padded rows ----
        {
            const unsigned char* slab = g_kbf + ((size_t)((b*9 + j)*2))*16384;
            for (int i = tid; i < 2048; i += 256) {
                int split = i >> 10, rem = i & 1023;
                int n = rem >> 3, seg = rem & 7;
                const unsigned char* src = slab + (size_t)split*16384 + n*128 + seg*16;
                unsigned dst = smb + B_HI + (unsigned)split*18432u
                             + (unsigned)(n*144 + seg*16);
                asm volatile("cp.async.cg.shared.global [%0],[%1],16;"
                             :: "r"(dst), "l"(src));
            }
        }
        asm volatile("cp.async.commit_group;");
        asm volatile("cp.async.wait_group 0;");
        __syncthreads();

        // ---- build A hi/lo (bf16 split, packed 32-bit stores, no conflicts) ----
        {
            int K0 = 64*j + 2*kk2;
            int ciA = K0/9,     kA = K0 - 9*ciA;
            int ciB = (K0+1)/9, kB = (K0+1) - 9*ciB;
            int cA = (ciA - ci0)*396 + (kA/3)*132 + (kA % 3);
            int cB = (ciB - ci0)*396 + (kB/3)*132 + (kB % 3);
            #pragma unroll 4
            for (int pxi = 0; pxi < 16; ++pxi) {
                int px = qq*16 + pxi;
                float vA = fc[cA + px], vB = fc[cB + px];
                __nv_bfloat16 hA = __float2bfloat16(vA);
                __nv_bfloat16 hB = __float2bfloat16(vB);
                __nv_bfloat16 lA = __float2bfloat16(vA - __bfloat162float(hA));
                __nv_bfloat16 lB = __float2bfloat16(vB - __bfloat162float(hB));
                unsigned off = (unsigned)(px*144 + kk2*4);
                *(uint32_t*)(dsm + A_HI + off) =
                    (uint32_t)__bfloat16_as_ushort(hA) | ((uint32_t)__bfloat16_as_ushort(hB) << 16);
                *(uint32_t*)(dsm + A_LO + off) =
                    (uint32_t)__bfloat16_as_ushort(lA) | ((uint32_t)__bfloat16_as_ushort(lB) << 16);
            }
        }
        __syncthreads();

        // ---- compute: 4 k16-steps; passes ah*bh, al*bh, ah*bl ----
        #pragma unroll
        for (int ks = 0; ks < 4; ++ks) {
            const unsigned kb = (unsigned)ks*32u;
            uint32_t ah[2][4], al2[2][4];
            #pragma unroll
            for (int mt = 0; mt < 2; ++mt) {
                LDSM4(ah[mt][0],ah[mt][1],ah[mt][2],ah[mt][3],
                      smb + A_HI + arow + (unsigned)mt*2304u + kb);
                LDSM4(al2[mt][0],al2[mt][1],al2[mt][2],al2[mt][3],
                      smb + A_LO + arow + (unsigned)mt*2304u + kb);
            }
            #pragma unroll
            for (int half = 0; half < 2; ++half) {
                uint32_t bb[2][4];
                // B_hi tiles: each x4 covers 16 n-rows -> stride 2304 B
                #pragma unroll
                for (int i = 0; i < 2; ++i)
                    LDSM4(bb[i][0],bb[i][1],bb[i][2],bb[i][3],
                          smb + B_HI + brow + (unsigned)(half*2 + i)*2304u + kb);
                #pragma unroll
                for (int mt = 0; mt < 2; ++mt)
                    #pragma unroll
                    for (int nt4 = 0; nt4 < 4; ++nt4) {
                        int nt = half*4 + nt4;
                        uint32_t b0 = bb[nt4 >> 1][(nt4 & 1)*2];
                        uint32_t b1 = bb[nt4 >> 1][(nt4 & 1)*2 + 1];
                        MMA(acc[mt][nt], ah[mt], b0, b1);
                        MMA(acc[mt][nt], al2[mt], b0, b1);
                    }
                // B_lo tiles
                #pragma unroll
                for (int i = 0; i < 2; ++i)
                    LDSM4(bb[i][0],bb[i][1],bb[i][2],bb[i][3],
                          smb + B_LO + brow + (unsigned)(half*2 + i)*2304u + kb);
                #pragma unroll
                for (int mt = 0; mt < 2; ++mt)
                    #pragma unroll
                    for (int nt4 = 0; nt4 < 4; ++nt4) {
                        int nt = half*4 + nt4;
                        uint32_t b0 = bb[nt4 >> 1][(nt4 & 1)*2];
                        uint32_t b1 = bb[nt4 >> 1][(nt4 & 1)*2 + 1];
                        MMA(acc[mt][nt], ah[mt], b0, b1);
                    }
            }
        }
    }

    // ---- epilogue: per-pixel r selection, direct register -> gmem ----
    const int pxw = warpM*32, nw = warpN*64;
    #pragma unroll
    for (int mt = 0; mt < 2; ++mt) {
        #pragma unroll
        for (int nt = 0; nt < 8; ++nt) {
            int n0 = nw + nt*8 + (l & 3)*2;
            int co = n0 & 63, rn = n0 >> 6;
            int px0 = pxw + mt*16 + (l >> 2);
            float* o = out + ((size_t)(b*COUT + co))*HW + y*128;
            if (s_rsel[px0] == rn) {
                o[px0]                = acc[mt][nt][0];
                o[(size_t)HW + px0]   = acc[mt][nt][1];
            }
            if (s_rsel[px0 + 8] == rn) {
                o[px0 + 8]              = acc[mt][nt][2];
                o[(size_t)HW + px0 + 8] = acc[mt][nt][3];
            }
        }
    }
}

// ---------------------------------------------------------------------------
// Launch: inputs in metadata order: feat, pred, w1, b1, w2, b2, gk
// ---------------------------------------------------------------------------
extern "C" void kernel_launch(void* const* d_in, const int* in_sizes, int n_in,
                              void* d_out, int out_size) {
    const float* feat = (const float*)d_in[0];
    const float* pred = (const float*)d_in[1];
    const float* w1   = (const float*)d_in[2];
    const float* b1   = (const float*)d_in[3];
    const float* w2   = (const float*)d_in[4];
    const float* b2   = (const float*)d_in[5];
    const float* gk   = (const float*)d_in[6];
    float* out = (float*)d_out;

    cudaFuncSetAttribute(conv_main_kernel,
                         cudaFuncAttributeMaxDynamicSharedMemorySize, CONV_DSMEM);

    poolsa_kernel<<<640, 256>>>(feat, pred, gk);
    kerngen_kernel<<<BB*2*9, 256>>>(w1, b1, w2, b2);

    dim3 gc(HH, BB);
    conv_main_kernel<<<gc, 256, CONV_DSMEM>>>(feat, pred, out);
}